// round 17
// baseline (speedup 1.0000x reference)
#include <cuda_runtime.h>
#include <cuda_bf16.h>
#include <cstdint>

#define TT 1024
#define BX 128
#define NIJ (BX * BX)
#define NCHUNK 146       // chunk 0: steps [0,8); chunk c>0: [7c+1, 7c+8)
#define BUFB 52224       // one tile buffer: A (64x272B) + B (128x272B)
#define B_OFF 17408      // B tile offset within a buffer

// scratch: local prefix products, layout [t][i*128+j]; 64 MB
__device__ float g_scratch[TT * NIJ];

__device__ __forceinline__ uint32_t smem_u32(const void* p) {
    uint32_t a;
    asm("{ .reg .u64 t; cvta.to.shared.u64 t, %1; cvt.u32.u64 %0, t; }"
        : "=r"(a) : "l"(p));
    return a;
}
__device__ __forceinline__ void ldsm_x4(uint32_t& r0, uint32_t& r1,
                                        uint32_t& r2, uint32_t& r3,
                                        uint32_t addr) {
    asm volatile("ldmatrix.sync.aligned.m8n8.x4.shared.b16 {%0,%1,%2,%3}, [%4];"
                 : "=r"(r0), "=r"(r1), "=r"(r2), "=r"(r3) : "r"(addr));
}
__device__ __forceinline__ void mma16816(float* c, const uint32_t* a,
                                         uint32_t b0, uint32_t b1) {
    asm volatile(
        "mma.sync.aligned.m16n8k16.row.col.f32.bf16.bf16.f32 "
        "{%0,%1,%2,%3}, {%4,%5,%6,%7}, {%8,%9}, {%0,%1,%2,%3};"
        : "+f"(c[0]), "+f"(c[1]), "+f"(c[2]), "+f"(c[3])
        : "r"(a[0]), "r"(a[1]), "r"(a[2]), "r"(a[3]), "r"(b0), "r"(b1));
}
__device__ __forceinline__ uint32_t bcat(__nv_bfloat16 a, __nv_bfloat16 b) {
    __nv_bfloat162 t = __halves2bfloat162(a, b);
    return *reinterpret_cast<uint32_t*>(&t);
}

// Convert step t's diffs into buffer (t & 1): A tile = this CTA's 64-row
// X half (x1023, hi|lo), B tile = all 128 Y rows (hi|lo). Thread role:
// xrow = tid>>2 (0..63), q = tid&3 (d-quad of 16).
__device__ __forceinline__ void convert_step(char* smc, int t, int ib,
                                             int xrow, int q,
                                             const float4* __restrict__ X4,
                                             const float4* __restrict__ Y4) {
    char* bufc = smc + (t & 1) * BUFB;
    // X half
    {
        const int gb = (ib + xrow) * 16384 + t * 16 + q * 4;
        float fx[16];
#pragma unroll
        for (int c = 0; c < 4; ++c) {
            float4 a0 = X4[gb + c], a1 = X4[gb + 16 + c];
            fx[4 * c + 0] = (a1.x - a0.x) * 1023.0f;
            fx[4 * c + 1] = (a1.y - a0.y) * 1023.0f;
            fx[4 * c + 2] = (a1.z - a0.z) * 1023.0f;
            fx[4 * c + 3] = (a1.w - a0.w) * 1023.0f;
        }
        uint32_t xh[8], xl[8];
#pragma unroll
        for (int m = 0; m < 8; ++m) {
            float u = fx[2 * m], v = fx[2 * m + 1];
            __nv_bfloat16 uh = __float2bfloat16_rn(u);
            __nv_bfloat16 vh = __float2bfloat16_rn(v);
            xh[m] = bcat(uh, vh);
            xl[m] = bcat(__float2bfloat16_rn(u - __bfloat162float(uh)),
                         __float2bfloat16_rn(v - __bfloat162float(vh)));
        }
        char* pa = bufc + xrow * 272 + q * 32;
        ((uint4*)pa)[0] = ((uint4*)xh)[0];
        ((uint4*)(pa + 16))[0] = ((uint4*)xh)[1];
        ((uint4*)(pa + 128))[0] = ((uint4*)xl)[0];
        ((uint4*)(pa + 144))[0] = ((uint4*)xl)[1];
    }
    // Y: two 64-row halves
#pragma unroll
    for (int h = 0; h < 2; ++h) {
        const int gb = (xrow + 64 * h) * 16384 + t * 16 + q * 4;
        float fy[16];
#pragma unroll
        for (int c = 0; c < 4; ++c) {
            float4 b0 = Y4[gb + c], b1 = Y4[gb + 16 + c];
            fy[4 * c + 0] = b1.x - b0.x;
            fy[4 * c + 1] = b1.y - b0.y;
            fy[4 * c + 2] = b1.z - b0.z;
            fy[4 * c + 3] = b1.w - b0.w;
        }
        uint32_t yh[8], yl[8];
#pragma unroll
        for (int m = 0; m < 8; ++m) {
            float p = fy[2 * m], r = fy[2 * m + 1];
            __nv_bfloat16 ph = __float2bfloat16_rn(p);
            __nv_bfloat16 rh = __float2bfloat16_rn(r);
            yh[m] = bcat(ph, rh);
            yl[m] = bcat(__float2bfloat16_rn(p - __bfloat162float(ph)),
                         __float2bfloat16_rn(r - __bfloat162float(rh)));
        }
        char* pb = bufc + B_OFF + (xrow + 64 * h) * 272 + q * 32;
        ((uint4*)pb)[0] = ((uint4*)yh)[0];
        ((uint4*)(pb + 16))[0] = ((uint4*)yh)[1];
        ((uint4*)(pb + 128))[0] = ((uint4*)yl)[0];
        ((uint4*)(pb + 144))[0] = ((uint4*)yl)[1];
    }
}

// Phase 1 (HMMA, pipelined, 2 CTAs/SM): 292 blocks; block -> (chunk = b>>1,
// i-half = (b&1)*64). Per step: bar -> ldsm+MMA(s) -> convert+STS(s+1)
// (LDG latency drains under HMMAs) -> EPI(s). Tiles double-buffered by s&1.
// The sibling CTA on the same SM fills the remaining barrier/EPI bubbles.
__global__ __launch_bounds__(256, 2)
void nsk_phase1(const float4* __restrict__ X4, const float4* __restrict__ Y4) {
    extern __shared__ char smc[];
    const uint32_t sb = smem_u32(smc);

    const int tid = threadIdx.x;
    const int wid = tid >> 5;
    const int lane = tid & 31;

    const int chunk = blockIdx.x >> 1;
    const int ib = (blockIdx.x & 1) << 6;    // i-half base: 0 or 64

    // conversion role
    const int xrow = tid >> 2;               // 0..63
    const int q = tid & 3;                   // d-quad of 16
    // mma tile role: 8 warps, 2x4
    const int m0 = (wid >> 2) << 5;          // 0 or 32 (within A tile)
    const int n0 = (wid & 3) << 5;
    const int grp = lane >> 3, lrow = lane & 7;
    const uint32_t offA = (uint32_t)((lrow + 8 * (grp & 1)) * 272 + 16 * (grp >> 1));
    const uint32_t offB = (uint32_t)((lrow + 8 * (grp >> 1)) * 272 + 16 * (grp & 1));
    const int g = lane >> 2, tg = lane & 3;

    const int s_start = (chunk == 0) ? 0 : 7 * chunk + 1;
    const int s_end = 7 * chunk + 8;         // max 1023

    float k[2][4][4];
#pragma unroll
    for (int a = 0; a < 2; a++)
#pragma unroll
        for (int c = 0; c < 4; c++)
#pragma unroll
            for (int e = 0; e < 4; e++) k[a][c][e] = 1.0f;

    // prologue: tiles for the first step
    convert_step(smc, s_start, ib, xrow, q, X4, Y4);

    for (int s = s_start; s < s_end; ++s) {
        __syncthreads();   // STS(s) complete; ldsm readers of buf (s+1)&1 done

        const uint32_t aA = sb + (s & 1) * BUFB;
        const uint32_t aB = aA + B_OFF;

        // ---- issue MMA(s): 4 k-chunks, hh + hl + lh
        float cacc[2][4][4];
#pragma unroll
        for (int mf = 0; mf < 2; mf++)
#pragma unroll
            for (int nf = 0; nf < 4; nf++)
#pragma unroll
                for (int e = 0; e < 4; e++) cacc[mf][nf][e] = 0.0f;

#pragma unroll
        for (int kc = 0; kc < 4; ++kc) {
            const uint32_t kh = kc * 32;
            const uint32_t kl = 128 + kc * 32;
            uint32_t ah0[4], ah1[4], al0[4], al1[4];
            uint32_t bh0[4], bh1[4], bl0[4], bl1[4];
            ldsm_x4(ah0[0], ah0[1], ah0[2], ah0[3], aA + m0 * 272 + kh + offA);
            ldsm_x4(ah1[0], ah1[1], ah1[2], ah1[3], aA + (m0 + 16) * 272 + kh + offA);
            ldsm_x4(al0[0], al0[1], al0[2], al0[3], aA + m0 * 272 + kl + offA);
            ldsm_x4(al1[0], al1[1], al1[2], al1[3], aA + (m0 + 16) * 272 + kl + offA);
            ldsm_x4(bh0[0], bh0[1], bh0[2], bh0[3], aB + n0 * 272 + kh + offB);
            ldsm_x4(bh1[0], bh1[1], bh1[2], bh1[3], aB + (n0 + 16) * 272 + kh + offB);
            ldsm_x4(bl0[0], bl0[1], bl0[2], bl0[3], aB + n0 * 272 + kl + offB);
            ldsm_x4(bl1[0], bl1[1], bl1[2], bl1[3], aB + (n0 + 16) * 272 + kl + offB);
            mma16816(cacc[0][0], ah0, bh0[0], bh0[1]);
            mma16816(cacc[0][1], ah0, bh0[2], bh0[3]);
            mma16816(cacc[0][2], ah0, bh1[0], bh1[1]);
            mma16816(cacc[0][3], ah0, bh1[2], bh1[3]);
            mma16816(cacc[1][0], ah1, bh0[0], bh0[1]);
            mma16816(cacc[1][1], ah1, bh0[2], bh0[3]);
            mma16816(cacc[1][2], ah1, bh1[0], bh1[1]);
            mma16816(cacc[1][3], ah1, bh1[2], bh1[3]);
            mma16816(cacc[0][0], ah0, bl0[0], bl0[1]);
            mma16816(cacc[0][1], ah0, bl0[2], bl0[3]);
            mma16816(cacc[0][2], ah0, bl1[0], bl1[1]);
            mma16816(cacc[0][3], ah0, bl1[2], bl1[3]);
            mma16816(cacc[1][0], ah1, bl0[0], bl0[1]);
            mma16816(cacc[1][1], ah1, bl0[2], bl0[3]);
            mma16816(cacc[1][2], ah1, bl1[0], bl1[1]);
            mma16816(cacc[1][3], ah1, bl1[2], bl1[3]);
            mma16816(cacc[0][0], al0, bh0[0], bh0[1]);
            mma16816(cacc[0][1], al0, bh0[2], bh0[3]);
            mma16816(cacc[0][2], al0, bh1[0], bh1[1]);
            mma16816(cacc[0][3], al0, bh1[2], bh1[3]);
            mma16816(cacc[1][0], al1, bh0[0], bh0[1]);
            mma16816(cacc[1][1], al1, bh0[2], bh0[3]);
            mma16816(cacc[1][2], al1, bh1[0], bh1[1]);
            mma16816(cacc[1][3], al1, bh1[2], bh1[3]);
        }

        // ---- convert+STS for step s+1 (overlaps HMMA drain)
        if (s + 1 < s_end)
            convert_step(smc, s + 1, ib, xrow, q, X4, Y4);

        // ---- epilogue: waits on HMMA results; k *= (1+z); float2 stores
        float* base = g_scratch + (size_t)(s + 1) * NIJ;
#pragma unroll
        for (int mf = 0; mf < 2; mf++) {
#pragma unroll
            for (int nf = 0; nf < 4; nf++) {
                const int i0 = ib + m0 + mf * 16 + g;
                const int j = n0 + nf * 8 + tg * 2;
                float* c4 = cacc[mf][nf];
                float* kk = k[mf][nf];
                float k0 = fmaf(c4[0], kk[0], kk[0]);
                float k1 = fmaf(c4[1], kk[1], kk[1]);
                float k2 = fmaf(c4[2], kk[2], kk[2]);
                float k3 = fmaf(c4[3], kk[3], kk[3]);
                kk[0] = k0; kk[1] = k1; kk[2] = k2; kk[3] = k3;
                *(float2*)(base + i0 * BX + j) = make_float2(k0, k1);
                *(float2*)(base + (i0 + 8) * BX + j) = make_float2(k2, k3);
            }
        }
    }
}

// Phase 2 (fused, verified R12 version): one block per 32-ij strip.
// Chunk c's last written t is e = 7c+8; owner of t>=1 is c = (t-2)/7.
__global__ __launch_bounds__(256, 8)
void nsk_phase2f(float* __restrict__ out) {
    extern __shared__ float sm[];
    float* cend = sm;                    // [146][32] -> exclusive scales
    float* qp = sm + NCHUNK * 32;        // [8][32]
    float* tile = qp + 8 * 32;           // [64][33]

    const int tid = threadIdx.x;
    const int lane = tid & 31;
    const int q = tid >> 5;              // 0..7
    const int lane64 = tid & 63;
    const int colg = tid >> 6;           // 0..3
    const int ij0 = blockIdx.x * 32;

#pragma unroll
    for (int cc = 0; cc < 19; cc++) {
        const int c = q + 8 * cc;
        if (c < NCHUNK) {
            const int e = 7 * c + 8;
            cend[c * 32 + lane] = g_scratch[(size_t)e * NIJ + ij0 + lane];
        }
    }
    __syncthreads();
    {
        float p = 1.0f;
#pragma unroll 1
        for (int cc = 0; cc < 19; cc++) {
            const int c = 19 * q + cc;
            if (c < NCHUNK) {
                const float v = cend[c * 32 + lane];
                cend[c * 32 + lane] = p;
                p *= v;
            }
        }
        qp[q * 32 + lane] = p;
    }
    __syncthreads();
    if (q > 0) {
        float off = qp[lane];
#pragma unroll
        for (int w = 1; w < 7; w++)
            if (q > w) off *= qp[w * 32 + lane];
#pragma unroll 1
        for (int cc = 0; cc < 19; cc++) {
            const int c = 19 * q + cc;
            if (c < NCHUNK) cend[c * 32 + lane] *= off;
        }
    }
    __syncthreads();

#pragma unroll 1
    for (int ti = 0; ti < 16; ti++) {
        const int t0 = ti * 64;
#pragma unroll
        for (int rr = 0; rr < 8; rr++) {
            const int r = q + 8 * rr;
            const int t = t0 + r;
            if (t == 0) {
                tile[r * 33 + lane] = 1.0f;
            } else {
                const int c = (t - 2) / 7;   // t=1 -> 0
                const float v = g_scratch[(size_t)t * NIJ + ij0 + lane];
                tile[r * 33 + lane] = v * cend[c * 32 + lane];
            }
        }
        __syncthreads();
#pragma unroll
        for (int cc = 0; cc < 8; cc++) {
            const int col = colg + 4 * cc;
            out[(size_t)(ij0 + col) * TT + t0 + lane64] = tile[lane64 * 33 + col];
        }
        __syncthreads();
    }
}

extern "C" void kernel_launch(void* const* d_in, const int* in_sizes, int n_in,
                              void* d_out, int out_size) {
    const float4* X4 = (const float4*)d_in[0];
    const float4* Y4 = (const float4*)d_in[1];
    float* out = (float*)d_out;

    const int smem1 = 2 * BUFB;                                               // 104448 B
    const int smem2 = (NCHUNK * 32 + 8 * 32 + 64 * 33) * (int)sizeof(float);  // 28160 B
    cudaFuncSetAttribute(nsk_phase1, cudaFuncAttributeMaxDynamicSharedMemorySize, smem1);
    cudaFuncSetAttribute(nsk_phase2f, cudaFuncAttributeMaxDynamicSharedMemorySize, smem2);

    nsk_phase1<<<2 * NCHUNK, 256, smem1>>>(X4, Y4);
    nsk_phase2f<<<NIJ / 32, 256, smem2>>>(out);
}